// round 2
// baseline (speedup 1.0000x reference)
#include <cuda_runtime.h>
#include <math.h>

// SimilarityTreeLSTM on GB300: level-parallel tree evaluation in one
// persistent kernel with a software grid barrier.
//
// Key ideas:
//  * depth-based scheduling (process levels deepest-first; all deps satisfied)
//  * vocab-level projection tables instead of per-node X@W GEMMs
//  * NB=8 nodes per block in the recurrent matvecs for 8x weight reuse
//  * __ldcg for all cross-block-communicated data (L1 store-allocate hazard)

#define NNODE 65536
#define TOT   (2 * NNODE)
#define M     256
#define M3    (3 * M)
#define VOCAB 1000
#define NB    8
#define MAXD_CAP 65536

// ---------------- device scratch (static: no allocations allowed) ----------
__device__ float g_hsum[TOT * M];        // 134 MB
__device__ float g_fcsum[TOT * M];       // 134 MB
__device__ float g_ioux[VOCAB * M3];     // vocab proj: emb@Wioux + bioux
__device__ float g_fxp[VOCAB * M];       // vocab proj: emb@Wfx + bfx
__device__ int   g_depth[TOT];
__device__ int   g_order[TOT];
__device__ int   g_hist[MAXD_CAP];
__device__ int   g_startv[MAXD_CAP];
__device__ int   g_cursor[MAXD_CAP];
__device__ int   g_maxd;
__device__ float g_croot[2 * M];
__device__ unsigned g_barcnt;
__device__ unsigned g_sense;

__device__ __forceinline__ float sigf(float x) {
    return 1.0f / (1.0f + expf(-x));
}

// Sense-reversal grid barrier. Safe: counter reset happens before sense bump,
// and arrivals at barrier k+1 are gated on release of barrier k.
__device__ __forceinline__ void gsync() {
    __syncthreads();
    if (threadIdx.x == 0) {
        __threadfence();
        unsigned target = *((volatile unsigned*)&g_sense) + 1u;
        unsigned a = atomicAdd(&g_barcnt, 1u);
        if (a == gridDim.x - 1u) {
            g_barcnt = 0u;
            __threadfence();
            atomicExch(&g_sense, target);
        } else {
            while (*((volatile unsigned*)&g_sense) != target) { __nanosleep(64); }
        }
        __threadfence();
    }
    __syncthreads();
}

extern "C" __global__ void __launch_bounds__(256, 1)
treelstm_kernel(const int* __restrict__ l_tok, const int* __restrict__ l_par,
                const int* __restrict__ r_tok, const int* __restrict__ r_par,
                const float* __restrict__ emb,
                const float* __restrict__ Wioux, const float* __restrict__ bioux,
                const float* __restrict__ Wiouh, const float* __restrict__ biouh,
                const float* __restrict__ Wfx,   const float* __restrict__ bfx,
                const float* __restrict__ Wfh,   const float* __restrict__ bfh,
                const float* __restrict__ Wh,    const float* __restrict__ bh,
                const float* __restrict__ Wp,    const float* __restrict__ bp,
                float* __restrict__ out)
{
    __shared__ __align__(16) float s_f[NB * M];   // 8 KB, multi-purpose
    __shared__ int s_node[NB], s_tok[NB], s_parg[NB], s_ptok[NB];

    const int t   = threadIdx.x;
    const int gid = blockIdx.x * blockDim.x + threadIdx.x;
    const int gs  = gridDim.x * blockDim.x;

    // ---------------- Phase 0: zero state + vocab projections ------------
    {
        float4 z4 = make_float4(0.f, 0.f, 0.f, 0.f);
        float4* h4 = reinterpret_cast<float4*>(g_hsum);
        float4* f4 = reinterpret_cast<float4*>(g_fcsum);
        const int n4 = TOT * M / 4;
        for (int i = gid; i < n4; i += gs) h4[i] = z4;
        for (int i = gid; i < n4; i += gs) f4[i] = z4;
        for (int i = gid; i < MAXD_CAP; i += gs) g_hist[i] = 0;
        if (gid == 0) g_maxd = 0;

        // vocab projections: groups of NB vocab rows per block
        const int VG = VOCAB / NB;   // 125
        for (int g = blockIdx.x; g < VG; g += gridDim.x) {
            #pragma unroll
            for (int n = 0; n < NB; n++)
                s_f[n * M + t] = emb[(g * NB + n) * M + t];
            __syncthreads();
            float a0[NB], a1[NB], a2[NB], af[NB];
            #pragma unroll
            for (int n = 0; n < NB; n++) {
                a0[n] = bioux[t]; a1[n] = bioux[M + t];
                a2[n] = bioux[2 * M + t]; af[n] = bfx[t];
            }
            #pragma unroll 1
            for (int k = 0; k < M; k += 4) {
                float4 x4[NB];
                #pragma unroll
                for (int n = 0; n < NB; n++)
                    x4[n] = *reinterpret_cast<const float4*>(s_f + n * M + k);
                #pragma unroll
                for (int kk = 0; kk < 4; kk++) {
                    float w0 = Wioux[(k + kk) * M3 + t];
                    float w1 = Wioux[(k + kk) * M3 + M + t];
                    float w2 = Wioux[(k + kk) * M3 + 2 * M + t];
                    float wf = Wfx[(k + kk) * M + t];
                    #pragma unroll
                    for (int n = 0; n < NB; n++) {
                        float xv = (kk == 0) ? x4[n].x : (kk == 1) ? x4[n].y
                                 : (kk == 2) ? x4[n].z : x4[n].w;
                        a0[n] += xv * w0; a1[n] += xv * w1;
                        a2[n] += xv * w2; af[n] += xv * wf;
                    }
                }
            }
            #pragma unroll
            for (int n = 0; n < NB; n++) {
                int v = g * NB + n;
                g_ioux[v * M3 + t]         = a0[n];
                g_ioux[v * M3 + M + t]     = a1[n];
                g_ioux[v * M3 + 2 * M + t] = a2[n];
                g_fxp[v * M + t]           = af[n];
            }
            __syncthreads();
        }
    }
    gsync();

    // ---------------- Phase 1: depth walk + histogram ---------------------
    for (int i = gid; i < TOT; i += gs) {
        int tree = i >> 16, loc = i & (NNODE - 1);
        const int* parp = tree ? r_par : l_par;
        int d = 0, j = loc;
        while (j) { j = __ldg(parp + j); d++; }
        g_depth[i] = d;
        atomicAdd(&g_hist[d], 1);
        atomicMax(&g_maxd, d);
    }
    gsync();

    // ---------------- Phase 2: serial scan of level offsets --------------
    if (blockIdx.x == 0 && threadIdx.x == 0) {
        int s = 0, md = __ldcg(&g_maxd);
        for (int d = 0; d <= md; d++) {
            g_startv[d] = s; g_cursor[d] = s;
            s += __ldcg(&g_hist[d]);
        }
    }
    gsync();

    // ---------------- Phase 3: scatter nodes into level buckets ----------
    for (int i = gid; i < TOT; i += gs) {
        int d = g_depth[i];
        int pos = atomicAdd(&g_cursor[d], 1);
        g_order[pos] = i;
    }
    gsync();

    // ---------------- Phase 4: level loop (deepest first) -----------------
    const int maxd = __ldcg(&g_maxd);
    for (int d = maxd; d >= 0; --d) {
        const int s0  = __ldcg(&g_startv[d]);
        const int cnt = __ldcg(&g_hist[d]);
        const int ngrp = (cnt + NB - 1) / NB;
        for (int g = blockIdx.x; g < ngrp; g += gridDim.x) {
            const int base = s0 + g * NB;
            const int nn   = min(NB, cnt - g * NB);
            if (t < NB) {
                int idx  = base + ((t < nn) ? t : 0);    // clamp (dup node 0 of grp)
                int node = g_order[idx];
                int tree = node >> 16, loc = node & (NNODE - 1);
                const int* tokp = tree ? r_tok : l_tok;
                const int* parp = tree ? r_par : l_par;
                int pl = parp[loc];
                s_node[t] = node;
                s_tok[t]  = tokp[loc];
                s_parg[t] = (tree << 16) + pl;
                s_ptok[t] = tokp[pl];
            }
            __syncthreads();
            // load h_sum rows (must bypass L1: updated via L2 atomics)
            #pragma unroll
            for (int n = 0; n < NB; n++)
                s_f[n * M + t] = __ldcg(&g_hsum[s_node[n] * M + t]);
            __syncthreads();

            float a0[NB], a1[NB], a2[NB];
            #pragma unroll
            for (int n = 0; n < NB; n++) {
                int tk = s_tok[n];
                a0[n] = g_ioux[tk * M3 + t]         + biouh[t];
                a1[n] = g_ioux[tk * M3 + M + t]     + biouh[M + t];
                a2[n] = g_ioux[tk * M3 + 2 * M + t] + biouh[2 * M + t];
            }
            #pragma unroll 1
            for (int k = 0; k < M; k += 4) {
                float4 h4[NB];
                #pragma unroll
                for (int n = 0; n < NB; n++)
                    h4[n] = *reinterpret_cast<const float4*>(s_f + n * M + k);
                #pragma unroll
                for (int kk = 0; kk < 4; kk++) {
                    float w0 = Wiouh[(k + kk) * M3 + t];
                    float w1 = Wiouh[(k + kk) * M3 + M + t];
                    float w2 = Wiouh[(k + kk) * M3 + 2 * M + t];
                    #pragma unroll
                    for (int n = 0; n < NB; n++) {
                        float hv = (kk == 0) ? h4[n].x : (kk == 1) ? h4[n].y
                                 : (kk == 2) ? h4[n].z : h4[n].w;
                        a0[n] += hv * w0; a1[n] += hv * w1; a2[n] += hv * w2;
                    }
                }
            }
            float cv[NB], hv[NB];
            #pragma unroll
            for (int n = 0; n < NB; n++) {
                float fc = __ldcg(&g_fcsum[s_node[n] * M + t]);
                float ig = sigf(a0[n]);
                float og = sigf(a1[n]);
                float ug = tanhf(a2[n]);
                cv[n] = ig * ug + fc;
                hv[n] = og * tanhf(cv[n]);
            }
            __syncthreads();                 // done reading s_f as h_sum
            #pragma unroll
            for (int n = 0; n < NB; n++) s_f[n * M + t] = hv[n];
            __syncthreads();

            float b[NB];
            #pragma unroll
            for (int n = 0; n < NB; n++)
                b[n] = bfh[t] + g_fxp[s_ptok[n] * M + t];
            #pragma unroll 1
            for (int k = 0; k < M; k += 4) {
                float4 h4[NB];
                #pragma unroll
                for (int n = 0; n < NB; n++)
                    h4[n] = *reinterpret_cast<const float4*>(s_f + n * M + k);
                #pragma unroll
                for (int kk = 0; kk < 4; kk++) {
                    float w = Wfh[(k + kk) * M + t];
                    #pragma unroll
                    for (int n = 0; n < NB; n++) {
                        float hx = (kk == 0) ? h4[n].x : (kk == 1) ? h4[n].y
                                 : (kk == 2) ? h4[n].z : h4[n].w;
                        b[n] += hx * w;
                    }
                }
            }
            #pragma unroll
            for (int n = 0; n < NB; n++) {
                if (n < nn) {
                    int node = s_node[n];
                    if (node & (NNODE - 1)) {        // not a root
                        float f = sigf(b[n]);
                        atomicAdd(&g_hsum[s_parg[n] * M + t], hv[n]);
                        atomicAdd(&g_fcsum[s_parg[n] * M + t], f * cv[n]);
                    } else {
                        g_croot[(node >> 16) * M + t] = cv[n];
                    }
                }
            }
            __syncthreads();
        }
        gsync();
    }

    // ---------------- Phase 5: similarity head (block 0) ------------------
    if (blockIdx.x == 0) {
        float cl = __ldcg(&g_croot[t]);
        float cr = __ldcg(&g_croot[M + t]);
        s_f[t]     = cl * cr;
        s_f[M + t] = fabsf(cl - cr);
        __syncthreads();
        float acc = bh[t];
        for (int k = 0; k < 2 * M; k++) acc += s_f[k] * Wh[k * M + t];
        float hid = sigf(acc);
        s_f[2 * M + t] = hid * Wp[2 * t];
        s_f[3 * M + t] = hid * Wp[2 * t + 1];
        __syncthreads();
        if (t == 0) {
            float l0 = bp[0], l1 = bp[1];
            for (int k = 0; k < M; k++) { l0 += s_f[2 * M + k]; l1 += s_f[3 * M + k]; }
            float mx = fmaxf(l0, l1);
            float e0 = expf(l0 - mx), e1 = expf(l1 - mx);
            float inv = 1.0f / (e0 + e1);
            out[0] = e0 * inv;
            out[1] = e1 * inv;
        }
    }
}

extern "C" void kernel_launch(void* const* d_in, const int* in_sizes, int n_in,
                              void* d_out, int out_size)
{
    (void)in_sizes; (void)n_in; (void)out_size;
    int dev = 0;
    cudaGetDevice(&dev);
    int nsm = 0;
    cudaDeviceGetAttribute(&nsm, cudaDevAttrMultiProcessorCount, dev);
    if (nsm <= 0) nsm = 148;

    treelstm_kernel<<<nsm, 256>>>(
        (const int*)d_in[0], (const int*)d_in[1],
        (const int*)d_in[2], (const int*)d_in[3],
        (const float*)d_in[4],
        (const float*)d_in[5], (const float*)d_in[6],
        (const float*)d_in[7], (const float*)d_in[8],
        (const float*)d_in[9], (const float*)d_in[10],
        (const float*)d_in[11], (const float*)d_in[12],
        (const float*)d_in[13], (const float*)d_in[14],
        (const float*)d_in[15], (const float*)d_in[16],
        (float*)d_out);
}

// round 3
// speedup vs baseline: 1.0013x; 1.0013x over previous
#include <cuda_runtime.h>
#include <math.h>

// SimilarityTreeLSTM on GB300: level-parallel tree evaluation in one
// persistent kernel with a software grid barrier.
//
// Key ideas:
//  * depth-based scheduling (process levels deepest-first; all deps satisfied)
//  * vocab-level projection tables instead of per-node X@W GEMMs
//  * NB=8 nodes per block in the recurrent matvecs for 8x weight reuse
//  * __ldcg for all cross-block-communicated data (L1 store-allocate hazard)

#define NNODE 65536
#define TOT   (2 * NNODE)
#define M     256
#define M3    (3 * M)
#define VOCAB 1000
#define NB    8
#define MAXD_CAP 65536

// ---------------- device scratch (static: no allocations allowed) ----------
__device__ float g_hsum[TOT * M];        // 134 MB
__device__ float g_fcsum[TOT * M];       // 134 MB
__device__ float g_ioux[VOCAB * M3];     // vocab proj: emb@Wioux + bioux
__device__ float g_fxp[VOCAB * M];       // vocab proj: emb@Wfx + bfx
__device__ int   g_depth[TOT];
__device__ int   g_order[TOT];
__device__ int   g_hist[MAXD_CAP];
__device__ int   g_startv[MAXD_CAP];
__device__ int   g_cursor[MAXD_CAP];
__device__ int   g_maxd;
__device__ float g_croot[2 * M];
__device__ unsigned g_barcnt;
__device__ unsigned g_sense;

__device__ __forceinline__ float sigf(float x) {
    return 1.0f / (1.0f + expf(-x));
}

// Sense-reversal grid barrier. Safe: counter reset happens before sense bump,
// and arrivals at barrier k+1 are gated on release of barrier k.
__device__ __forceinline__ void gsync() {
    __syncthreads();
    if (threadIdx.x == 0) {
        __threadfence();
        unsigned target = *((volatile unsigned*)&g_sense) + 1u;
        unsigned a = atomicAdd(&g_barcnt, 1u);
        if (a == gridDim.x - 1u) {
            g_barcnt = 0u;
            __threadfence();
            atomicExch(&g_sense, target);
        } else {
            while (*((volatile unsigned*)&g_sense) != target) { __nanosleep(64); }
        }
        __threadfence();
    }
    __syncthreads();
}

extern "C" __global__ void __launch_bounds__(256, 1)
treelstm_kernel(const int* __restrict__ l_tok, const int* __restrict__ l_par,
                const int* __restrict__ r_tok, const int* __restrict__ r_par,
                const float* __restrict__ emb,
                const float* __restrict__ Wioux, const float* __restrict__ bioux,
                const float* __restrict__ Wiouh, const float* __restrict__ biouh,
                const float* __restrict__ Wfx,   const float* __restrict__ bfx,
                const float* __restrict__ Wfh,   const float* __restrict__ bfh,
                const float* __restrict__ Wh,    const float* __restrict__ bh,
                const float* __restrict__ Wp,    const float* __restrict__ bp,
                float* __restrict__ out)
{
    __shared__ __align__(16) float s_f[NB * M];   // 8 KB, multi-purpose
    __shared__ int s_node[NB], s_tok[NB], s_parg[NB], s_ptok[NB];

    const int t   = threadIdx.x;
    const int gid = blockIdx.x * blockDim.x + threadIdx.x;
    const int gs  = gridDim.x * blockDim.x;

    // ---------------- Phase 0: zero state + vocab projections ------------
    {
        float4 z4 = make_float4(0.f, 0.f, 0.f, 0.f);
        float4* h4 = reinterpret_cast<float4*>(g_hsum);
        float4* f4 = reinterpret_cast<float4*>(g_fcsum);
        const int n4 = TOT * M / 4;
        for (int i = gid; i < n4; i += gs) h4[i] = z4;
        for (int i = gid; i < n4; i += gs) f4[i] = z4;
        for (int i = gid; i < MAXD_CAP; i += gs) g_hist[i] = 0;
        if (gid == 0) g_maxd = 0;

        // vocab projections: groups of NB vocab rows per block
        const int VG = VOCAB / NB;   // 125
        for (int g = blockIdx.x; g < VG; g += gridDim.x) {
            #pragma unroll
            for (int n = 0; n < NB; n++)
                s_f[n * M + t] = emb[(g * NB + n) * M + t];
            __syncthreads();
            float a0[NB], a1[NB], a2[NB], af[NB];
            #pragma unroll
            for (int n = 0; n < NB; n++) {
                a0[n] = bioux[t]; a1[n] = bioux[M + t];
                a2[n] = bioux[2 * M + t]; af[n] = bfx[t];
            }
            #pragma unroll 1
            for (int k = 0; k < M; k += 4) {
                float4 x4[NB];
                #pragma unroll
                for (int n = 0; n < NB; n++)
                    x4[n] = *reinterpret_cast<const float4*>(s_f + n * M + k);
                #pragma unroll
                for (int kk = 0; kk < 4; kk++) {
                    float w0 = Wioux[(k + kk) * M3 + t];
                    float w1 = Wioux[(k + kk) * M3 + M + t];
                    float w2 = Wioux[(k + kk) * M3 + 2 * M + t];
                    float wf = Wfx[(k + kk) * M + t];
                    #pragma unroll
                    for (int n = 0; n < NB; n++) {
                        float xv = (kk == 0) ? x4[n].x : (kk == 1) ? x4[n].y
                                 : (kk == 2) ? x4[n].z : x4[n].w;
                        a0[n] += xv * w0; a1[n] += xv * w1;
                        a2[n] += xv * w2; af[n] += xv * wf;
                    }
                }
            }
            #pragma unroll
            for (int n = 0; n < NB; n++) {
                int v = g * NB + n;
                g_ioux[v * M3 + t]         = a0[n];
                g_ioux[v * M3 + M + t]     = a1[n];
                g_ioux[v * M3 + 2 * M + t] = a2[n];
                g_fxp[v * M + t]           = af[n];
            }
            __syncthreads();
        }
    }
    gsync();

    // ---------------- Phase 1: depth walk + histogram ---------------------
    for (int i = gid; i < TOT; i += gs) {
        int tree = i >> 16, loc = i & (NNODE - 1);
        const int* parp = tree ? r_par : l_par;
        int d = 0, j = loc;
        while (j) { j = __ldg(parp + j); d++; }
        g_depth[i] = d;
        atomicAdd(&g_hist[d], 1);
        atomicMax(&g_maxd, d);
    }
    gsync();

    // ---------------- Phase 2: serial scan of level offsets --------------
    if (blockIdx.x == 0 && threadIdx.x == 0) {
        int s = 0, md = __ldcg(&g_maxd);
        for (int d = 0; d <= md; d++) {
            g_startv[d] = s; g_cursor[d] = s;
            s += __ldcg(&g_hist[d]);
        }
    }
    gsync();

    // ---------------- Phase 3: scatter nodes into level buckets ----------
    for (int i = gid; i < TOT; i += gs) {
        int d = g_depth[i];
        int pos = atomicAdd(&g_cursor[d], 1);
        g_order[pos] = i;
    }
    gsync();

    // ---------------- Phase 4: level loop (deepest first) -----------------
    const int maxd = __ldcg(&g_maxd);
    for (int d = maxd; d >= 0; --d) {
        const int s0  = __ldcg(&g_startv[d]);
        const int cnt = __ldcg(&g_hist[d]);
        const int ngrp = (cnt + NB - 1) / NB;
        for (int g = blockIdx.x; g < ngrp; g += gridDim.x) {
            const int base = s0 + g * NB;
            const int nn   = min(NB, cnt - g * NB);
            if (t < NB) {
                int idx  = base + ((t < nn) ? t : 0);    // clamp (dup node 0 of grp)
                int node = g_order[idx];
                int tree = node >> 16, loc = node & (NNODE - 1);
                const int* tokp = tree ? r_tok : l_tok;
                const int* parp = tree ? r_par : l_par;
                int pl = parp[loc];
                s_node[t] = node;
                s_tok[t]  = tokp[loc];
                s_parg[t] = (tree << 16) + pl;
                s_ptok[t] = tokp[pl];
            }
            __syncthreads();
            // load h_sum rows (must bypass L1: updated via L2 atomics)
            #pragma unroll
            for (int n = 0; n < NB; n++)
                s_f[n * M + t] = __ldcg(&g_hsum[s_node[n] * M + t]);
            __syncthreads();

            float a0[NB], a1[NB], a2[NB];
            #pragma unroll
            for (int n = 0; n < NB; n++) {
                int tk = s_tok[n];
                a0[n] = g_ioux[tk * M3 + t]         + biouh[t];
                a1[n] = g_ioux[tk * M3 + M + t]     + biouh[M + t];
                a2[n] = g_ioux[tk * M3 + 2 * M + t] + biouh[2 * M + t];
            }
            #pragma unroll 1
            for (int k = 0; k < M; k += 4) {
                float4 h4[NB];
                #pragma unroll
                for (int n = 0; n < NB; n++)
                    h4[n] = *reinterpret_cast<const float4*>(s_f + n * M + k);
                #pragma unroll
                for (int kk = 0; kk < 4; kk++) {
                    float w0 = Wiouh[(k + kk) * M3 + t];
                    float w1 = Wiouh[(k + kk) * M3 + M + t];
                    float w2 = Wiouh[(k + kk) * M3 + 2 * M + t];
                    #pragma unroll
                    for (int n = 0; n < NB; n++) {
                        float hv = (kk == 0) ? h4[n].x : (kk == 1) ? h4[n].y
                                 : (kk == 2) ? h4[n].z : h4[n].w;
                        a0[n] += hv * w0; a1[n] += hv * w1; a2[n] += hv * w2;
                    }
                }
            }
            float cv[NB], hv[NB];
            #pragma unroll
            for (int n = 0; n < NB; n++) {
                float fc = __ldcg(&g_fcsum[s_node[n] * M + t]);
                float ig = sigf(a0[n]);
                float og = sigf(a1[n]);
                float ug = tanhf(a2[n]);
                cv[n] = ig * ug + fc;
                hv[n] = og * tanhf(cv[n]);
            }
            __syncthreads();                 // done reading s_f as h_sum
            #pragma unroll
            for (int n = 0; n < NB; n++) s_f[n * M + t] = hv[n];
            __syncthreads();

            float b[NB];
            #pragma unroll
            for (int n = 0; n < NB; n++)
                b[n] = bfh[t] + g_fxp[s_ptok[n] * M + t];
            #pragma unroll 1
            for (int k = 0; k < M; k += 4) {
                float4 h4[NB];
                #pragma unroll
                for (int n = 0; n < NB; n++)
                    h4[n] = *reinterpret_cast<const float4*>(s_f + n * M + k);
                #pragma unroll
                for (int kk = 0; kk < 4; kk++) {
                    float w = Wfh[(k + kk) * M + t];
                    #pragma unroll
                    for (int n = 0; n < NB; n++) {
                        float hx = (kk == 0) ? h4[n].x : (kk == 1) ? h4[n].y
                                 : (kk == 2) ? h4[n].z : h4[n].w;
                        b[n] += hx * w;
                    }
                }
            }
            #pragma unroll
            for (int n = 0; n < NB; n++) {
                if (n < nn) {
                    int node = s_node[n];
                    if (node & (NNODE - 1)) {        // not a root
                        float f = sigf(b[n]);
                        atomicAdd(&g_hsum[s_parg[n] * M + t], hv[n]);
                        atomicAdd(&g_fcsum[s_parg[n] * M + t], f * cv[n]);
                    } else {
                        g_croot[(node >> 16) * M + t] = cv[n];
                    }
                }
            }
            __syncthreads();
        }
        gsync();
    }

    // ---------------- Phase 5: similarity head (block 0) ------------------
    if (blockIdx.x == 0) {
        float cl = __ldcg(&g_croot[t]);
        float cr = __ldcg(&g_croot[M + t]);
        s_f[t]     = cl * cr;
        s_f[M + t] = fabsf(cl - cr);
        __syncthreads();
        float acc = bh[t];
        for (int k = 0; k < 2 * M; k++) acc += s_f[k] * Wh[k * M + t];
        float hid = sigf(acc);
        s_f[2 * M + t] = hid * Wp[2 * t];
        s_f[3 * M + t] = hid * Wp[2 * t + 1];
        __syncthreads();
        if (t == 0) {
            float l0 = bp[0], l1 = bp[1];
            for (int k = 0; k < M; k++) { l0 += s_f[2 * M + k]; l1 += s_f[3 * M + k]; }
            float mx = fmaxf(l0, l1);
            float e0 = expf(l0 - mx), e1 = expf(l1 - mx);
            float inv = 1.0f / (e0 + e1);
            out[0] = e0 * inv;
            out[1] = e1 * inv;
        }
    }
}

extern "C" void kernel_launch(void* const* d_in, const int* in_sizes, int n_in,
                              void* d_out, int out_size)
{
    (void)in_sizes; (void)n_in; (void)out_size;
    int dev = 0;
    cudaGetDevice(&dev);
    int nsm = 0;
    cudaDeviceGetAttribute(&nsm, cudaDevAttrMultiProcessorCount, dev);
    if (nsm <= 0) nsm = 148;

    treelstm_kernel<<<nsm, 256>>>(
        (const int*)d_in[0], (const int*)d_in[1],
        (const int*)d_in[2], (const int*)d_in[3],
        (const float*)d_in[4],
        (const float*)d_in[5], (const float*)d_in[6],
        (const float*)d_in[7], (const float*)d_in[8],
        (const float*)d_in[9], (const float*)d_in[10],
        (const float*)d_in[11], (const float*)d_in[12],
        (const float*)d_in[13], (const float*)d_in[14],
        (const float*)d_in[15], (const float*)d_in[16],
        (float*)d_out);
}

// round 4
// speedup vs baseline: 1.1043x; 1.1029x over previous
#include <cuda_runtime.h>
#include <math.h>

// SimilarityTreeLSTM on GB300: level-parallel tree evaluation in one
// persistent kernel with a software grid barrier.
//
// R3 changes vs R1:
//  * 2 CTAs/SM (grid = 2*nsm, __launch_bounds__(256,2)) -> 4 warps/SMSP
//  * register double-buffering of weight loads in both recurrent matvecs
//    (prefetch next k-group's weights during current FMA burst)

#define NNODE 65536
#define TOT   (2 * NNODE)
#define M     256
#define M3    (3 * M)
#define VOCAB 1000
#define NB    8
#define MAXD_CAP 65536

// ---------------- device scratch (static: no allocations allowed) ----------
__device__ float g_hsum[TOT * M];        // 134 MB
__device__ float g_fcsum[TOT * M];       // 134 MB
__device__ float g_ioux[VOCAB * M3];     // vocab proj: emb@Wioux + bioux
__device__ float g_fxp[VOCAB * M];       // vocab proj: emb@Wfx + bfx
__device__ int   g_depth[TOT];
__device__ int   g_order[TOT];
__device__ int   g_hist[MAXD_CAP];
__device__ int   g_startv[MAXD_CAP];
__device__ int   g_cursor[MAXD_CAP];
__device__ int   g_maxd;
__device__ float g_croot[2 * M];
__device__ unsigned g_barcnt;
__device__ unsigned g_sense;

__device__ __forceinline__ float sigf(float x) {
    return 1.0f / (1.0f + expf(-x));
}

// Sense-reversal grid barrier. Requires all blocks co-resident.
__device__ __forceinline__ void gsync() {
    __syncthreads();
    if (threadIdx.x == 0) {
        __threadfence();
        unsigned target = *((volatile unsigned*)&g_sense) + 1u;
        unsigned a = atomicAdd(&g_barcnt, 1u);
        if (a == gridDim.x - 1u) {
            g_barcnt = 0u;
            __threadfence();
            atomicExch(&g_sense, target);
        } else {
            while (*((volatile unsigned*)&g_sense) != target) { __nanosleep(64); }
        }
        __threadfence();
    }
    __syncthreads();
}

extern "C" __global__ void __launch_bounds__(256, 2)
treelstm_kernel(const int* __restrict__ l_tok, const int* __restrict__ l_par,
                const int* __restrict__ r_tok, const int* __restrict__ r_par,
                const float* __restrict__ emb,
                const float* __restrict__ Wioux, const float* __restrict__ bioux,
                const float* __restrict__ Wiouh, const float* __restrict__ biouh,
                const float* __restrict__ Wfx,   const float* __restrict__ bfx,
                const float* __restrict__ Wfh,   const float* __restrict__ bfh,
                const float* __restrict__ Wh,    const float* __restrict__ bh,
                const float* __restrict__ Wp,    const float* __restrict__ bp,
                float* __restrict__ out)
{
    __shared__ __align__(16) float s_f[NB * M];   // 8 KB, multi-purpose
    __shared__ int s_node[NB], s_tok[NB], s_parg[NB], s_ptok[NB];

    const int t   = threadIdx.x;
    const int gid = blockIdx.x * blockDim.x + threadIdx.x;
    const int gs  = gridDim.x * blockDim.x;

    // ---------------- Phase 0: zero state + vocab projections ------------
    {
        float4 z4 = make_float4(0.f, 0.f, 0.f, 0.f);
        float4* h4 = reinterpret_cast<float4*>(g_hsum);
        float4* f4 = reinterpret_cast<float4*>(g_fcsum);
        const int n4 = TOT * M / 4;
        for (int i = gid; i < n4; i += gs) h4[i] = z4;
        for (int i = gid; i < n4; i += gs) f4[i] = z4;
        for (int i = gid; i < MAXD_CAP; i += gs) g_hist[i] = 0;
        if (gid == 0) g_maxd = 0;

        // vocab projections: groups of NB vocab rows per block
        const int VG = VOCAB / NB;   // 125
        for (int g = blockIdx.x; g < VG; g += gridDim.x) {
            #pragma unroll
            for (int n = 0; n < NB; n++)
                s_f[n * M + t] = emb[(g * NB + n) * M + t];
            __syncthreads();
            float a0[NB], a1[NB], a2[NB], af[NB];
            #pragma unroll
            for (int n = 0; n < NB; n++) {
                a0[n] = bioux[t]; a1[n] = bioux[M + t];
                a2[n] = bioux[2 * M + t]; af[n] = bfx[t];
            }
            #pragma unroll 1
            for (int k = 0; k < M; k += 4) {
                float4 x4[NB];
                #pragma unroll
                for (int n = 0; n < NB; n++)
                    x4[n] = *reinterpret_cast<const float4*>(s_f + n * M + k);
                #pragma unroll
                for (int kk = 0; kk < 4; kk++) {
                    float w0 = Wioux[(k + kk) * M3 + t];
                    float w1 = Wioux[(k + kk) * M3 + M + t];
                    float w2 = Wioux[(k + kk) * M3 + 2 * M + t];
                    float wf = Wfx[(k + kk) * M + t];
                    #pragma unroll
                    for (int n = 0; n < NB; n++) {
                        float xv = (kk == 0) ? x4[n].x : (kk == 1) ? x4[n].y
                                 : (kk == 2) ? x4[n].z : x4[n].w;
                        a0[n] += xv * w0; a1[n] += xv * w1;
                        a2[n] += xv * w2; af[n] += xv * wf;
                    }
                }
            }
            #pragma unroll
            for (int n = 0; n < NB; n++) {
                int v = g * NB + n;
                g_ioux[v * M3 + t]         = a0[n];
                g_ioux[v * M3 + M + t]     = a1[n];
                g_ioux[v * M3 + 2 * M + t] = a2[n];
                g_fxp[v * M + t]           = af[n];
            }
            __syncthreads();
        }
    }
    gsync();

    // ---------------- Phase 1: depth walk + histogram ---------------------
    for (int i = gid; i < TOT; i += gs) {
        int tree = i >> 16, loc = i & (NNODE - 1);
        const int* parp = tree ? r_par : l_par;
        int d = 0, j = loc;
        while (j) { j = __ldg(parp + j); d++; }
        g_depth[i] = d;
        atomicAdd(&g_hist[d], 1);
        atomicMax(&g_maxd, d);
    }
    gsync();

    // ---------------- Phase 2: serial scan of level offsets --------------
    if (blockIdx.x == 0 && threadIdx.x == 0) {
        int s = 0, md = __ldcg(&g_maxd);
        for (int d = 0; d <= md; d++) {
            g_startv[d] = s; g_cursor[d] = s;
            s += __ldcg(&g_hist[d]);
        }
    }
    gsync();

    // ---------------- Phase 3: scatter nodes into level buckets ----------
    for (int i = gid; i < TOT; i += gs) {
        int d = g_depth[i];
        int pos = atomicAdd(&g_cursor[d], 1);
        g_order[pos] = i;
    }
    gsync();

    // ---------------- Phase 4: level loop (deepest first) -----------------
    const int maxd = __ldcg(&g_maxd);
    for (int d = maxd; d >= 0; --d) {
        const int s0  = __ldcg(&g_startv[d]);
        const int cnt = __ldcg(&g_hist[d]);
        const int ngrp = (cnt + NB - 1) / NB;
        for (int g = blockIdx.x; g < ngrp; g += gridDim.x) {
            const int base = s0 + g * NB;
            const int nn   = min(NB, cnt - g * NB);
            if (t < NB) {
                int idx  = base + ((t < nn) ? t : 0);    // clamp (dup node 0 of grp)
                int node = g_order[idx];
                int tree = node >> 16, loc = node & (NNODE - 1);
                const int* tokp = tree ? r_tok : l_tok;
                const int* parp = tree ? r_par : l_par;
                int pl = parp[loc];
                s_node[t] = node;
                s_tok[t]  = tokp[loc];
                s_parg[t] = (tree << 16) + pl;
                s_ptok[t] = tokp[pl];
            }
            __syncthreads();
            // load h_sum rows (must bypass L1: updated via L2 atomics)
            #pragma unroll
            for (int n = 0; n < NB; n++)
                s_f[n * M + t] = __ldcg(&g_hsum[s_node[n] * M + t]);
            __syncthreads();

            float a0[NB], a1[NB], a2[NB];
            #pragma unroll
            for (int n = 0; n < NB; n++) {
                int tk = s_tok[n];
                a0[n] = g_ioux[tk * M3 + t]         + biouh[t];
                a1[n] = g_ioux[tk * M3 + M + t]     + biouh[M + t];
                a2[n] = g_ioux[tk * M3 + 2 * M + t] + biouh[2 * M + t];
            }

            // ---- Wiouh matvec with register double-buffered weights ----
            {
                float w0[2][4], w1[2][4], w2[2][4];
                #pragma unroll
                for (int kk = 0; kk < 4; kk++) {
                    w0[0][kk] = Wiouh[kk * M3 + t];
                    w1[0][kk] = Wiouh[kk * M3 + M + t];
                    w2[0][kk] = Wiouh[kk * M3 + 2 * M + t];
                }
                #pragma unroll 1
                for (int k = 0; k < M; k += 4) {
                    const int cur = (k >> 2) & 1;
                    const int nxt = cur ^ 1;
                    if (k + 4 < M) {
                        #pragma unroll
                        for (int kk = 0; kk < 4; kk++) {
                            w0[nxt][kk] = Wiouh[(k + 4 + kk) * M3 + t];
                            w1[nxt][kk] = Wiouh[(k + 4 + kk) * M3 + M + t];
                            w2[nxt][kk] = Wiouh[(k + 4 + kk) * M3 + 2 * M + t];
                        }
                    }
                    float4 h4[NB];
                    #pragma unroll
                    for (int n = 0; n < NB; n++)
                        h4[n] = *reinterpret_cast<const float4*>(s_f + n * M + k);
                    #pragma unroll
                    for (int kk = 0; kk < 4; kk++) {
                        #pragma unroll
                        for (int n = 0; n < NB; n++) {
                            float hv = (kk == 0) ? h4[n].x : (kk == 1) ? h4[n].y
                                     : (kk == 2) ? h4[n].z : h4[n].w;
                            a0[n] += hv * w0[cur][kk];
                            a1[n] += hv * w1[cur][kk];
                            a2[n] += hv * w2[cur][kk];
                        }
                    }
                }
            }

            float cv[NB], hv[NB];
            #pragma unroll
            for (int n = 0; n < NB; n++) {
                float fc = __ldcg(&g_fcsum[s_node[n] * M + t]);
                float ig = sigf(a0[n]);
                float og = sigf(a1[n]);
                float ug = tanhf(a2[n]);
                cv[n] = ig * ug + fc;
                hv[n] = og * tanhf(cv[n]);
            }
            __syncthreads();                 // done reading s_f as h_sum
            #pragma unroll
            for (int n = 0; n < NB; n++) s_f[n * M + t] = hv[n];
            __syncthreads();

            float b[NB];
            #pragma unroll
            for (int n = 0; n < NB; n++)
                b[n] = bfh[t] + g_fxp[s_ptok[n] * M + t];

            // ---- Wfh matvec with register double-buffered weights ----
            {
                float wf[2][4];
                #pragma unroll
                for (int kk = 0; kk < 4; kk++)
                    wf[0][kk] = Wfh[kk * M + t];
                #pragma unroll 1
                for (int k = 0; k < M; k += 4) {
                    const int cur = (k >> 2) & 1;
                    const int nxt = cur ^ 1;
                    if (k + 4 < M) {
                        #pragma unroll
                        for (int kk = 0; kk < 4; kk++)
                            wf[nxt][kk] = Wfh[(k + 4 + kk) * M + t];
                    }
                    float4 h4[NB];
                    #pragma unroll
                    for (int n = 0; n < NB; n++)
                        h4[n] = *reinterpret_cast<const float4*>(s_f + n * M + k);
                    #pragma unroll
                    for (int kk = 0; kk < 4; kk++) {
                        #pragma unroll
                        for (int n = 0; n < NB; n++) {
                            float hx = (kk == 0) ? h4[n].x : (kk == 1) ? h4[n].y
                                     : (kk == 2) ? h4[n].z : h4[n].w;
                            b[n] += hx * wf[cur][kk];
                        }
                    }
                }
            }

            #pragma unroll
            for (int n = 0; n < NB; n++) {
                if (n < nn) {
                    int node = s_node[n];
                    if (node & (NNODE - 1)) {        // not a root
                        float f = sigf(b[n]);
                        atomicAdd(&g_hsum[s_parg[n] * M + t], hv[n]);
                        atomicAdd(&g_fcsum[s_parg[n] * M + t], f * cv[n]);
                    } else {
                        g_croot[(node >> 16) * M + t] = cv[n];
                    }
                }
            }
            __syncthreads();
        }
        gsync();
    }

    // ---------------- Phase 5: similarity head (block 0) ------------------
    if (blockIdx.x == 0) {
        float cl = __ldcg(&g_croot[t]);
        float cr = __ldcg(&g_croot[M + t]);
        s_f[t]     = cl * cr;
        s_f[M + t] = fabsf(cl - cr);
        __syncthreads();
        float acc = bh[t];
        for (int k = 0; k < 2 * M; k++) acc += s_f[k] * Wh[k * M + t];
        float hid = sigf(acc);
        s_f[2 * M + t] = hid * Wp[2 * t];
        s_f[3 * M + t] = hid * Wp[2 * t + 1];
        __syncthreads();
        if (t == 0) {
            float l0 = bp[0], l1 = bp[1];
            for (int k = 0; k < M; k++) { l0 += s_f[2 * M + k]; l1 += s_f[3 * M + k]; }
            float mx = fmaxf(l0, l1);
            float e0 = expf(l0 - mx), e1 = expf(l1 - mx);
            float inv = 1.0f / (e0 + e1);
            out[0] = e0 * inv;
            out[1] = e1 * inv;
        }
    }
}

extern "C" void kernel_launch(void* const* d_in, const int* in_sizes, int n_in,
                              void* d_out, int out_size)
{
    (void)in_sizes; (void)n_in; (void)out_size;
    int dev = 0;
    cudaGetDevice(&dev);
    int nsm = 0;
    cudaDeviceGetAttribute(&nsm, cudaDevAttrMultiProcessorCount, dev);
    if (nsm <= 0) nsm = 148;

    treelstm_kernel<<<2 * nsm, 256>>>(
        (const int*)d_in[0], (const int*)d_in[1],
        (const int*)d_in[2], (const int*)d_in[3],
        (const float*)d_in[4],
        (const float*)d_in[5], (const float*)d_in[6],
        (const float*)d_in[7], (const float*)d_in[8],
        (const float*)d_in[9], (const float*)d_in[10],
        (const float*)d_in[11], (const float*)d_in[12],
        (const float*)d_in[13], (const float*)d_in[14],
        (const float*)d_in[15], (const float*)d_in[16],
        (float*)d_out);
}

// round 5
// speedup vs baseline: 1.6714x; 1.5135x over previous
#include <cuda_runtime.h>
#include <math.h>

// SimilarityTreeLSTM on GB300: level-parallel tree evaluation in one
// persistent kernel with a software grid barrier.
//
// R4 changes vs R3:
//  * NB 8 -> 16 nodes per block: halves L2 weight traffic (the co-equal
//    floor identified in R4 ncu), doubles FMA per weight load
//  * explicit two-phase (wa/wb) weight double-buffer (no dynamic indexing
//    that ptxas could demote to local memory)
//  * node-inner FMA loop keeps live registers ~90 (< 128 cap @ 2 CTA/SM)
//  * loop-invariant bias loads hoisted out of the group loop

#define NNODE 65536
#define TOT   (2 * NNODE)
#define M     256
#define M3    (3 * M)
#define VOCAB 1000
#define NB    16
#define VNB   8
#define MAXD_CAP 65536

// ---------------- device scratch (static: no allocations allowed) ----------
__device__ float g_hsum[TOT * M];        // 134 MB
__device__ float g_fcsum[TOT * M];       // 134 MB
__device__ float g_ioux[VOCAB * M3];     // vocab proj: emb@Wioux + bioux
__device__ float g_fxp[VOCAB * M];       // vocab proj: emb@Wfx + bfx
__device__ int   g_depth[TOT];
__device__ int   g_order[TOT];
__device__ int   g_hist[MAXD_CAP];
__device__ int   g_startv[MAXD_CAP];
__device__ int   g_cursor[MAXD_CAP];
__device__ int   g_maxd;
__device__ float g_croot[2 * M];
__device__ unsigned g_barcnt;
__device__ unsigned g_sense;

__device__ __forceinline__ float sigf(float x) {
    return 1.0f / (1.0f + expf(-x));
}

// Sense-reversal grid barrier. Requires all blocks co-resident.
__device__ __forceinline__ void gsync() {
    __syncthreads();
    if (threadIdx.x == 0) {
        __threadfence();
        unsigned target = *((volatile unsigned*)&g_sense) + 1u;
        unsigned a = atomicAdd(&g_barcnt, 1u);
        if (a == gridDim.x - 1u) {
            g_barcnt = 0u;
            __threadfence();
            atomicExch(&g_sense, target);
        } else {
            while (*((volatile unsigned*)&g_sense) != target) { __nanosleep(64); }
        }
        __threadfence();
    }
    __syncthreads();
}

extern "C" __global__ void __launch_bounds__(256, 2)
treelstm_kernel(const int* __restrict__ l_tok, const int* __restrict__ l_par,
                const int* __restrict__ r_tok, const int* __restrict__ r_par,
                const float* __restrict__ emb,
                const float* __restrict__ Wioux, const float* __restrict__ bioux,
                const float* __restrict__ Wiouh, const float* __restrict__ biouh,
                const float* __restrict__ Wfx,   const float* __restrict__ bfx,
                const float* __restrict__ Wfh,   const float* __restrict__ bfh,
                const float* __restrict__ Wh,    const float* __restrict__ bh,
                const float* __restrict__ Wp,    const float* __restrict__ bp,
                float* __restrict__ out)
{
    __shared__ __align__(16) float s_f[NB * M];   // 16 KB, multi-purpose
    __shared__ int s_node[NB], s_tok[NB], s_parg[NB], s_ptok[NB];

    const int t   = threadIdx.x;
    const int gid = blockIdx.x * blockDim.x + threadIdx.x;
    const int gs  = gridDim.x * blockDim.x;

    // ---------------- Phase 0: zero state + vocab projections ------------
    {
        float4 z4 = make_float4(0.f, 0.f, 0.f, 0.f);
        float4* h4p = reinterpret_cast<float4*>(g_hsum);
        float4* f4p = reinterpret_cast<float4*>(g_fcsum);
        const int n4 = TOT * M / 4;
        for (int i = gid; i < n4; i += gs) h4p[i] = z4;
        for (int i = gid; i < n4; i += gs) f4p[i] = z4;
        for (int i = gid; i < MAXD_CAP; i += gs) g_hist[i] = 0;
        if (gid == 0) g_maxd = 0;

        // vocab projections: groups of VNB vocab rows per block
        const int VG = VOCAB / VNB;   // 125
        for (int g = blockIdx.x; g < VG; g += gridDim.x) {
            #pragma unroll
            for (int n = 0; n < VNB; n++)
                s_f[n * M + t] = emb[(g * VNB + n) * M + t];
            __syncthreads();
            float a0[VNB], a1[VNB], a2[VNB], af[VNB];
            #pragma unroll
            for (int n = 0; n < VNB; n++) {
                a0[n] = bioux[t]; a1[n] = bioux[M + t];
                a2[n] = bioux[2 * M + t]; af[n] = bfx[t];
            }
            #pragma unroll 1
            for (int k = 0; k < M; k += 4) {
                #pragma unroll
                for (int kk = 0; kk < 4; kk++) {
                    float w0 = Wioux[(k + kk) * M3 + t];
                    float w1 = Wioux[(k + kk) * M3 + M + t];
                    float w2 = Wioux[(k + kk) * M3 + 2 * M + t];
                    float wf = Wfx[(k + kk) * M + t];
                    #pragma unroll
                    for (int n = 0; n < VNB; n++) {
                        float xv = s_f[n * M + k + kk];
                        a0[n] += xv * w0; a1[n] += xv * w1;
                        a2[n] += xv * w2; af[n] += xv * wf;
                    }
                }
            }
            #pragma unroll
            for (int n = 0; n < VNB; n++) {
                int v = g * VNB + n;
                g_ioux[v * M3 + t]         = a0[n];
                g_ioux[v * M3 + M + t]     = a1[n];
                g_ioux[v * M3 + 2 * M + t] = a2[n];
                g_fxp[v * M + t]           = af[n];
            }
            __syncthreads();
        }
    }
    gsync();

    // ---------------- Phase 1: depth walk + histogram ---------------------
    for (int i = gid; i < TOT; i += gs) {
        int tree = i >> 16, loc = i & (NNODE - 1);
        const int* parp = tree ? r_par : l_par;
        int d = 0, j = loc;
        while (j) { j = __ldg(parp + j); d++; }
        g_depth[i] = d;
        atomicAdd(&g_hist[d], 1);
        atomicMax(&g_maxd, d);
    }
    gsync();

    // ---------------- Phase 2: serial scan of level offsets --------------
    if (blockIdx.x == 0 && threadIdx.x == 0) {
        int s = 0, md = __ldcg(&g_maxd);
        for (int d = 0; d <= md; d++) {
            g_startv[d] = s; g_cursor[d] = s;
            s += __ldcg(&g_hist[d]);
        }
    }
    gsync();

    // ---------------- Phase 3: scatter nodes into level buckets ----------
    for (int i = gid; i < TOT; i += gs) {
        int d = g_depth[i];
        int pos = atomicAdd(&g_cursor[d], 1);
        g_order[pos] = i;
    }
    gsync();

    // loop-invariant biases
    const float bio0 = biouh[t], bio1 = biouh[M + t], bio2 = biouh[2 * M + t];
    const float bfh_t = bfh[t];

    // ---------------- Phase 4: level loop (deepest first) -----------------
    const int maxd = __ldcg(&g_maxd);
    for (int d = maxd; d >= 0; --d) {
        const int s0  = __ldcg(&g_startv[d]);
        const int cnt = __ldcg(&g_hist[d]);
        const int ngrp = (cnt + NB - 1) / NB;
        for (int g = blockIdx.x; g < ngrp; g += gridDim.x) {
            const int base = s0 + g * NB;
            const int nn   = min(NB, cnt - g * NB);
            if (t < NB) {
                int idx  = base + ((t < nn) ? t : 0);    // clamp (dup node 0 of grp)
                int node = g_order[idx];
                int tree = node >> 16, loc = node & (NNODE - 1);
                const int* tokp = tree ? r_tok : l_tok;
                const int* parp = tree ? r_par : l_par;
                int pl = parp[loc];
                s_node[t] = node;
                s_tok[t]  = tokp[loc];
                s_parg[t] = (tree << 16) + pl;
                s_ptok[t] = tokp[pl];
            }
            __syncthreads();
            // load h_sum rows (must bypass L1: updated via L2 atomics)
            #pragma unroll
            for (int n = 0; n < NB; n++)
                s_f[n * M + t] = __ldcg(&g_hsum[s_node[n] * M + t]);
            __syncthreads();

            float a0[NB], a1[NB], a2[NB];
            #pragma unroll
            for (int n = 0; n < NB; n++) {
                int tk = s_tok[n];
                a0[n] = g_ioux[tk * M3 + t]         + bio0;
                a1[n] = g_ioux[tk * M3 + M + t]     + bio1;
                a2[n] = g_ioux[tk * M3 + 2 * M + t] + bio2;
            }

            // ---- Wiouh matvec: explicit two-phase weight double-buffer ----
            {
                float wa0[4], wa1[4], wa2[4], wb0[4], wb1[4], wb2[4];
                #pragma unroll
                for (int kk = 0; kk < 4; kk++) {
                    wa0[kk] = Wiouh[kk * M3 + t];
                    wa1[kk] = Wiouh[kk * M3 + M + t];
                    wa2[kk] = Wiouh[kk * M3 + 2 * M + t];
                }
                #pragma unroll 1
                for (int k = 0; k < M; k += 8) {
                    // prefetch phase-B weights (k+4 always < M for k <= M-8)
                    #pragma unroll
                    for (int kk = 0; kk < 4; kk++) {
                        wb0[kk] = Wiouh[(k + 4 + kk) * M3 + t];
                        wb1[kk] = Wiouh[(k + 4 + kk) * M3 + M + t];
                        wb2[kk] = Wiouh[(k + 4 + kk) * M3 + 2 * M + t];
                    }
                    #pragma unroll
                    for (int n = 0; n < NB; n++) {
                        const float4 h4 = *reinterpret_cast<const float4*>(s_f + n * M + k);
                        a0[n] += h4.x * wa0[0]; a1[n] += h4.x * wa1[0]; a2[n] += h4.x * wa2[0];
                        a0[n] += h4.y * wa0[1]; a1[n] += h4.y * wa1[1]; a2[n] += h4.y * wa2[1];
                        a0[n] += h4.z * wa0[2]; a1[n] += h4.z * wa1[2]; a2[n] += h4.z * wa2[2];
                        a0[n] += h4.w * wa0[3]; a1[n] += h4.w * wa1[3]; a2[n] += h4.w * wa2[3];
                    }
                    // prefetch next phase-A weights
                    if (k + 8 < M) {
                        #pragma unroll
                        for (int kk = 0; kk < 4; kk++) {
                            wa0[kk] = Wiouh[(k + 8 + kk) * M3 + t];
                            wa1[kk] = Wiouh[(k + 8 + kk) * M3 + M + t];
                            wa2[kk] = Wiouh[(k + 8 + kk) * M3 + 2 * M + t];
                        }
                    }
                    #pragma unroll
                    for (int n = 0; n < NB; n++) {
                        const float4 h4 = *reinterpret_cast<const float4*>(s_f + n * M + k + 4);
                        a0[n] += h4.x * wb0[0]; a1[n] += h4.x * wb1[0]; a2[n] += h4.x * wb2[0];
                        a0[n] += h4.y * wb0[1]; a1[n] += h4.y * wb1[1]; a2[n] += h4.y * wb2[1];
                        a0[n] += h4.z * wb0[2]; a1[n] += h4.z * wb1[2]; a2[n] += h4.z * wb2[2];
                        a0[n] += h4.w * wb0[3]; a1[n] += h4.w * wb1[3]; a2[n] += h4.w * wb2[3];
                    }
                }
            }

            float cv[NB], hv[NB];
            #pragma unroll
            for (int n = 0; n < NB; n++) {
                float fc = __ldcg(&g_fcsum[s_node[n] * M + t]);
                float ig = sigf(a0[n]);
                float og = sigf(a1[n]);
                float ug = tanhf(a2[n]);
                cv[n] = ig * ug + fc;
                hv[n] = og * tanhf(cv[n]);
            }
            __syncthreads();                 // done reading s_f as h_sum
            #pragma unroll
            for (int n = 0; n < NB; n++) s_f[n * M + t] = hv[n];
            __syncthreads();

            float b[NB];
            #pragma unroll
            for (int n = 0; n < NB; n++)
                b[n] = bfh_t + g_fxp[s_ptok[n] * M + t];

            // ---- Wfh matvec: explicit two-phase weight double-buffer ----
            {
                float wa[4], wb[4];
                #pragma unroll
                for (int kk = 0; kk < 4; kk++)
                    wa[kk] = Wfh[kk * M + t];
                #pragma unroll 1
                for (int k = 0; k < M; k += 8) {
                    #pragma unroll
                    for (int kk = 0; kk < 4; kk++)
                        wb[kk] = Wfh[(k + 4 + kk) * M + t];
                    #pragma unroll
                    for (int n = 0; n < NB; n++) {
                        const float4 h4 = *reinterpret_cast<const float4*>(s_f + n * M + k);
                        b[n] += h4.x * wa[0] + h4.y * wa[1] + h4.z * wa[2] + h4.w * wa[3];
                    }
                    if (k + 8 < M) {
                        #pragma unroll
                        for (int kk = 0; kk < 4; kk++)
                            wa[kk] = Wfh[(k + 8 + kk) * M + t];
                    }
                    #pragma unroll
                    for (int n = 0; n < NB; n++) {
                        const float4 h4 = *reinterpret_cast<const float4*>(s_f + n * M + k + 4);
                        b[n] += h4.x * wb[0] + h4.y * wb[1] + h4.z * wb[2] + h4.w * wb[3];
                    }
                }
            }

            #pragma unroll
            for (int n = 0; n < NB; n++) {
                if (n < nn) {
                    int node = s_node[n];
                    if (node & (NNODE - 1)) {        // not a root
                        float f = sigf(b[n]);
                        atomicAdd(&g_hsum[s_parg[n] * M + t], hv[n]);
                        atomicAdd(&g_fcsum[s_parg[n] * M + t], f * cv[n]);
                    } else {
                        g_croot[(node >> 16) * M + t] = cv[n];
                    }
                }
            }
            __syncthreads();
        }
        gsync();
    }

    // ---------------- Phase 5: similarity head (block 0) ------------------
    if (blockIdx.x == 0) {
        float cl = __ldcg(&g_croot[t]);
        float cr = __ldcg(&g_croot[M + t]);
        s_f[t]     = cl * cr;
        s_f[M + t] = fabsf(cl - cr);
        __syncthreads();
        float acc = bh[t];
        for (int k = 0; k < 2 * M; k++) acc += s_f[k] * Wh[k * M + t];
        float hid = sigf(acc);
        s_f[2 * M + t] = hid * Wp[2 * t];
        s_f[3 * M + t] = hid * Wp[2 * t + 1];
        __syncthreads();
        if (t == 0) {
            float l0 = bp[0], l1 = bp[1];
            for (int k = 0; k < M; k++) { l0 += s_f[2 * M + k]; l1 += s_f[3 * M + k]; }
            float mx = fmaxf(l0, l1);
            float e0 = expf(l0 - mx), e1 = expf(l1 - mx);
            float inv = 1.0f / (e0 + e1);
            out[0] = e0 * inv;
            out[1] = e1 * inv;
        }
    }
}

extern "C" void kernel_launch(void* const* d_in, const int* in_sizes, int n_in,
                              void* d_out, int out_size)
{
    (void)in_sizes; (void)n_in; (void)out_size;
    int dev = 0;
    cudaGetDevice(&dev);
    int nsm = 0;
    cudaDeviceGetAttribute(&nsm, cudaDevAttrMultiProcessorCount, dev);
    if (nsm <= 0) nsm = 148;

    treelstm_kernel<<<2 * nsm, 256>>>(
        (const int*)d_in[0], (const int*)d_in[1],
        (const int*)d_in[2], (const int*)d_in[3],
        (const float*)d_in[4],
        (const float*)d_in[5], (const float*)d_in[6],
        (const float*)d_in[7], (const float*)d_in[8],
        (const float*)d_in[9], (const float*)d_in[10],
        (const float*)d_in[11], (const float*)d_in[12],
        (const float*)d_in[13], (const float*)d_in[14],
        (const float*)d_in[15], (const float*)d_in[16],
        (float*)d_out);
}